// round 4
// baseline (speedup 1.0000x reference)
#include <cuda_runtime.h>
#include <cstddef>

#define NGS 10
#define XMAX 512.0f
#define YMAX 384.0f
#define MTFD 1.0f

// Per-group broadcast parameters staged in shared memory.
struct __align__(8) GroupP {
    float l, wl, wr, wt, wb, rr, sln, scos, ssin;
    int   isl;
};

__global__ __launch_bounds__(256)
void mapping_kernel(const float* __restrict__ var,        // [B, 40]
                    const float* __restrict__ slider_len, // [10]
                    const float* __restrict__ scos_in,    // [10]
                    const float* __restrict__ ssin_in,    // [10]
                    const float* __restrict__ note_dist,  // [10]
                    const float* __restrict__ tick_diff,  // [10]
                    const float* __restrict__ start_pos,  // [2]
                    const int*   __restrict__ is_slider,  // [10]
                    float* __restrict__ out,              // [B, 10, 6]
                    int B)
{
    __shared__ GroupP gp[NGS];
    __shared__ float s_px0, s_py0;

    int t = threadIdx.x;
    if (t < NGS) {
        float l = 1.0f * note_dist[t];        // LMUL = 1.0
        GroupP g;
        g.l    = l;
        g.wl   = 0.05f * XMAX + 0.5f * l;
        g.wr   = 0.95f * XMAX - 0.5f * l;
        g.wt   = 0.05f * YMAX + 0.5f * l;
        g.wb   = 0.95f * YMAX - 0.5f * l;
        g.rr   = (tick_diff[t] <= MTFD) ? 0.0f : 1.0f;  // rerand = 1 - use_ds
        // NOTE: use_ds = (tick_diff <= MTFD); rerand = 1 - use_ds
        g.rr   = 1.0f - ((tick_diff[t] <= MTFD) ? 1.0f : 0.0f);
        g.sln  = slider_len[t];
        g.scos = scos_in[t];
        g.ssin = ssin_in[t];
        g.isl  = is_slider[t];
        gp[t] = g;
    }
    if (t == 0) { s_px0 = start_pos[0]; s_py0 = start_pos[1]; }
    __syncthreads();

    int i = blockIdx.x * blockDim.x + t;
    if (i >= B) return;

    // Load the full 40-float row as 10 float4 (coalesced-ish; warp covers a
    // dense 5120B region, every byte consumed -> full line utilization).
    float v[40];
    {
        const float4* __restrict__ vin = reinterpret_cast<const float4*>(var) + (size_t)i * 10;
        float4* vv = reinterpret_cast<float4*>(v);
#pragma unroll
        for (int j = 0; j < 10; j++) vv[j] = vin[j];
    }

    float px = s_px0, py = s_py0;

    float2* __restrict__ out2 = reinterpret_cast<float2*>(out) + (size_t)i * 30;

    const float invX = 1.0f / XMAX;
    const float invY = 1.0f / YMAX;

#pragma unroll
    for (int k = 0; k < NGS; k++) {
        const GroupP g = gp[k];
        const float rr = g.rr;
        const float nr = 1.0f - rr;

        const float vk  = v[k];         // var[:, k]
        const float vh  = v[10 + k];    // var[:, 10+k]  (cos_raw second half)
        const float vk2 = v[20 + k];    // var[:, 20+k]  (sin_raw first half)
        const float vh2 = v[30 + k];    // var[:, 30+k]  (sin_raw second half)

        // Normalized direction vectors
        const float inv1 = rsqrtf(vk * vk + vk2 * vk2);
        const float ck = vk  * inv1;
        const float sk = vk2 * inv1;
        const float inv2 = rsqrtf(vh * vh + vh2 * vh2);
        const float a = vh  * inv2;     // ckh
        const float b = vh2 * inv2;     // skh

        const float rerand_x = 256.0f + 256.0f * vk;
        const float rerand_y = 192.0f + 192.0f * vk2;

        const float dx = g.l * ck;
        const float dy = g.l * sk;

        // Wall predicates — exact replication of reference semantics
        const float wv_l  = (px < g.wl) ? 1.0f : 0.0f;
        const float wv_r  = (px > g.wr) ? 1.0f : 0.0f;
        const float wv_xm = ((px > g.wl) && (px < g.wr)) ? 1.0f : 0.0f;
        const float wv_t  = (py < g.wt) ? 1.0f : 0.0f;
        const float wv_b  = (py > g.wb) ? 1.0f : 0.0f;
        const float wv_ym = ((py > g.wt) && (py < g.wb)) ? 1.0f : 0.0f;

        const float adx = fabsf(dx);
        const float ady = fabsf(dy);
        const float x_delta = adx * wv_l - adx * wv_r + dx * wv_xm;
        const float y_delta = ady * wv_t - ady * wv_b + dy * wv_ym;

        const float x = rr * rerand_x + nr * (px + x_delta);
        const float y = rr * rerand_y + nr * (py + y_delta);

        float o0 = x * invX;
        float o1 = y * invY;
        float o2, o3, o4, o5;
        if (g.isl) {
            o2 = a * g.scos - b * g.ssin;
            o3 = a * g.ssin + b * g.scos;
            o4 = (x + a * g.sln) * invX;
            o5 = (y + b * g.sln) * invY;
        } else {
            o2 = rr * a + nr * ck;
            o3 = rr * b + nr * sk;
            o4 = o0;
            o5 = o1;
        }

        out2[k * 3 + 0] = make_float2(o0, o1);
        out2[k * 3 + 1] = make_float2(o2, o3);
        out2[k * 3 + 2] = make_float2(o4, o5);

        // NFSE == False  =>  carry is always (_x, _y)
        px = x;
        py = y;
    }
}

extern "C" void kernel_launch(void* const* d_in, const int* in_sizes, int n_in,
                              void* d_out, int out_size)
{
    const float* var        = (const float*)d_in[0];
    const float* slider_len = (const float*)d_in[1];
    const float* scos       = (const float*)d_in[2];
    const float* ssin       = (const float*)d_in[3];
    const float* note_dist  = (const float*)d_in[4];
    const float* tick_diff  = (const float*)d_in[5];
    const float* start_pos  = (const float*)d_in[6];
    const int*   is_slider  = (const int*)d_in[7];
    float* out = (float*)d_out;

    int B = in_sizes[0] / (4 * NGS);
    int threads = 256;
    int blocks = (B + threads - 1) / threads;
    mapping_kernel<<<blocks, threads>>>(var, slider_len, scos, ssin, note_dist,
                                        tick_diff, start_pos, is_slider, out, B);
}

// round 7
// speedup vs baseline: 2.1858x; 2.1858x over previous
#include <cuda_runtime.h>
#include <cstddef>

#define NGS 10
#define XMAX 512.0f
#define YMAX 384.0f
#define MTFD 1.0f

#define ROWS_PER_BLK 256
#define PAD_IN  41   // 40 + 1  -> stride mod 32 = 9 (coprime): conflict-free row reads
#define PAD_OUT 62   // 60 + 2  -> even (8B-aligned float2), 30t mod 32 distinct per phase
#define SMEM_IN_FLOATS  (ROWS_PER_BLK * PAD_IN)    // 10496 floats = 41984 B
#define SMEM_OUT_FLOATS (ROWS_PER_BLK * PAD_OUT)   // 15872 floats = 63488 B
#define SMEM_TOTAL_BYTES ((SMEM_IN_FLOATS + SMEM_OUT_FLOATS) * 4)  // 105472 B

// Per-group broadcast parameters staged in shared memory.
struct __align__(8) GroupP {
    float l, wl, wr, wt, wb, rr, sln, scos, ssin;
    int   isl;
};

__global__ __launch_bounds__(256)
void mapping_kernel(const float* __restrict__ var,        // [B, 40]
                    const float* __restrict__ slider_len, // [10]
                    const float* __restrict__ scos_in,    // [10]
                    const float* __restrict__ ssin_in,    // [10]
                    const float* __restrict__ note_dist,  // [10]
                    const float* __restrict__ tick_diff,  // [10]
                    const float* __restrict__ start_pos,  // [2]
                    const int*   __restrict__ is_slider,  // [10]
                    float* __restrict__ out,              // [B, 10, 6]
                    int B)
{
    extern __shared__ float smem[];
    float* s_in  = smem;                    // [256][41]
    float* s_out = smem + SMEM_IN_FLOATS;   // [256][62]

    __shared__ GroupP gp[NGS];
    __shared__ float s_px0, s_py0;

    const int t = threadIdx.x;
    if (t < NGS) {
        float l = 1.0f * note_dist[t];        // LMUL = 1.0
        GroupP g;
        g.l    = l;
        g.wl   = 0.05f * XMAX + 0.5f * l;
        g.wr   = 0.95f * XMAX - 0.5f * l;
        g.wt   = 0.05f * YMAX + 0.5f * l;
        g.wb   = 0.95f * YMAX - 0.5f * l;
        g.rr   = 1.0f - ((tick_diff[t] <= MTFD) ? 1.0f : 0.0f);  // rerand
        g.sln  = slider_len[t];
        g.scos = scos_in[t];
        g.ssin = ssin_in[t];
        g.isl  = is_slider[t];
        gp[t] = g;
    }
    if (t == 0) { s_px0 = start_pos[0]; s_py0 = start_pos[1]; }

    // ---------- Stage 1: cooperative coalesced load of the 256x40 tile ----------
    {
        const size_t f4base = (size_t)blockIdx.x * (ROWS_PER_BLK * 10);  // float4 units
        const size_t f4limit = (size_t)B * 10;
        const float4* __restrict__ vin = reinterpret_cast<const float4*>(var);
#pragma unroll
        for (int it = 0; it < 10; it++) {
            int li = it * ROWS_PER_BLK + t;         // 0..2559 local float4 idx
            size_t gidx = f4base + (size_t)li;
            if (gidx < f4limit) {
                float4 x = vin[gidx];
                int r = li / 10;                    // local row
                int c = (li % 10) * 4;              // col within row
                float* p = s_in + r * PAD_IN + c;
                p[0] = x.x; p[1] = x.y; p[2] = x.z; p[3] = x.w;
            }
        }
    }
    __syncthreads();

    // ---------- Stage 2: per-row scan (one thread per row) ----------
    const int row_global = blockIdx.x * ROWS_PER_BLK + t;
    if (row_global < B) {
        const float* __restrict__ v = s_in + t * PAD_IN;
        float2* __restrict__ so = reinterpret_cast<float2*>(s_out + t * PAD_OUT);

        float px = s_px0, py = s_py0;
        const float invX = 1.0f / XMAX;
        const float invY = 1.0f / YMAX;

#pragma unroll
        for (int k = 0; k < NGS; k++) {
            const GroupP g = gp[k];
            const float rr = g.rr;
            const float nr = 1.0f - rr;

            const float vk  = v[k];         // var[:, k]
            const float vh  = v[10 + k];    // var[:, 10+k]
            const float vk2 = v[20 + k];    // var[:, 20+k]
            const float vh2 = v[30 + k];    // var[:, 30+k]

            const float inv1 = rsqrtf(vk * vk + vk2 * vk2);
            const float ck = vk  * inv1;
            const float sk = vk2 * inv1;
            const float inv2 = rsqrtf(vh * vh + vh2 * vh2);
            const float a = vh  * inv2;     // ckh
            const float b = vh2 * inv2;     // skh

            const float rerand_x = 256.0f + 256.0f * vk;
            const float rerand_y = 192.0f + 192.0f * vk2;

            const float dx = g.l * ck;
            const float dy = g.l * sk;

            const float wv_l  = (px < g.wl) ? 1.0f : 0.0f;
            const float wv_r  = (px > g.wr) ? 1.0f : 0.0f;
            const float wv_xm = ((px > g.wl) && (px < g.wr)) ? 1.0f : 0.0f;
            const float wv_t  = (py < g.wt) ? 1.0f : 0.0f;
            const float wv_b  = (py > g.wb) ? 1.0f : 0.0f;
            const float wv_ym = ((py > g.wt) && (py < g.wb)) ? 1.0f : 0.0f;

            const float adx = fabsf(dx);
            const float ady = fabsf(dy);
            const float x_delta = adx * wv_l - adx * wv_r + dx * wv_xm;
            const float y_delta = ady * wv_t - ady * wv_b + dy * wv_ym;

            const float x = rr * rerand_x + nr * (px + x_delta);
            const float y = rr * rerand_y + nr * (py + y_delta);

            float o0 = x * invX;
            float o1 = y * invY;
            float o2, o3, o4, o5;
            if (g.isl) {
                o2 = a * g.scos - b * g.ssin;
                o3 = a * g.ssin + b * g.scos;
                o4 = (x + a * g.sln) * invX;
                o5 = (y + b * g.sln) * invY;
            } else {
                o2 = rr * a + nr * ck;
                o3 = rr * b + nr * sk;
                o4 = o0;
                o5 = o1;
            }

            so[k * 3 + 0] = make_float2(o0, o1);
            so[k * 3 + 1] = make_float2(o2, o3);
            so[k * 3 + 2] = make_float2(o4, o5);

            // NFSE == False => carry is always (_x, _y)
            px = x;
            py = y;
        }
    }
    __syncthreads();

    // ---------- Stage 3: cooperative coalesced flush of the 256x60 tile ----------
    {
        const size_t f2base = (size_t)blockIdx.x * (ROWS_PER_BLK * 30);  // float2 units
        const size_t f2limit = (size_t)B * 30;
        float2* __restrict__ og = reinterpret_cast<float2*>(out);
#pragma unroll
        for (int it = 0; it < 30; it++) {
            int li = it * ROWS_PER_BLK + t;         // 0..7679 local float2 idx
            size_t gidx = f2base + (size_t)li;
            if (gidx < f2limit) {
                int r = li / 30;
                int c = li % 30;                    // float2 column
                float2 val = *reinterpret_cast<const float2*>(s_out + r * PAD_OUT + c * 2);
                og[gidx] = val;
            }
        }
    }
}

extern "C" void kernel_launch(void* const* d_in, const int* in_sizes, int n_in,
                              void* d_out, int out_size)
{
    const float* var        = (const float*)d_in[0];
    const float* slider_len = (const float*)d_in[1];
    const float* scos       = (const float*)d_in[2];
    const float* ssin       = (const float*)d_in[3];
    const float* note_dist  = (const float*)d_in[4];
    const float* tick_diff  = (const float*)d_in[5];
    const float* start_pos  = (const float*)d_in[6];
    const int*   is_slider  = (const int*)d_in[7];
    float* out = (float*)d_out;

    int B = in_sizes[0] / (4 * NGS);

    static bool attr_set = false;
    if (!attr_set) {
        cudaFuncSetAttribute(mapping_kernel,
                             cudaFuncAttributeMaxDynamicSharedMemorySize,
                             SMEM_TOTAL_BYTES);
        attr_set = true;
    }

    int threads = ROWS_PER_BLK;
    int blocks = (B + threads - 1) / threads;
    mapping_kernel<<<blocks, threads, SMEM_TOTAL_BYTES>>>(
        var, slider_len, scos, ssin, note_dist,
        tick_diff, start_pos, is_slider, out, B);
}

// round 10
// speedup vs baseline: 2.7613x; 1.2633x over previous
#include <cuda_runtime.h>
#include <cstddef>

#define NGS 10
#define XMAX 512.0f
#define YMAX 384.0f
#define MTFD 1.0f

#define ROWS_PER_BLK 256
#define PAD_OUT 62   // 60 + 2 -> even (8B-aligned float2), conflict-free per-row STS.64
#define SMEM_OUT_FLOATS (ROWS_PER_BLK * PAD_OUT)   // 15872 floats = 63488 B
#define SMEM_TOTAL_BYTES (SMEM_OUT_FLOATS * 4)

// Per-group broadcast parameters staged in shared memory.
struct __align__(8) GroupP {
    float l, wl, wr, wt, wb, rr, sln, scos, ssin;
    int   isl;
};

__global__ __launch_bounds__(256, 3)
void mapping_kernel(const float* __restrict__ var,        // [B, 40]
                    const float* __restrict__ slider_len, // [10]
                    const float* __restrict__ scos_in,    // [10]
                    const float* __restrict__ ssin_in,    // [10]
                    const float* __restrict__ note_dist,  // [10]
                    const float* __restrict__ tick_diff,  // [10]
                    const float* __restrict__ start_pos,  // [2]
                    const int*   __restrict__ is_slider,  // [10]
                    float* __restrict__ out,              // [B, 10, 6]
                    int B)
{
    extern __shared__ float s_out[];        // [256][62]
    __shared__ GroupP gp[NGS];
    __shared__ float s_px0, s_py0;

    const int t = threadIdx.x;
    const int row = blockIdx.x * ROWS_PER_BLK + t;
    const bool active = (row < B);

    // ---- Issue this thread's row load FIRST (10 x LDG.128, deep MLP) ----
    float4 rv[10];
    if (active) {
        const float4* __restrict__ vin =
            reinterpret_cast<const float4*>(var) + (size_t)row * 10;
#pragma unroll
        for (int j = 0; j < 10; j++) rv[j] = vin[j];
    }

    // ---- Per-group broadcast params (overlaps with the LDG burst above) ----
    if (t < NGS) {
        float l = 1.0f * note_dist[t];        // LMUL = 1.0
        GroupP g;
        g.l    = l;
        g.wl   = 0.05f * XMAX + 0.5f * l;
        g.wr   = 0.95f * XMAX - 0.5f * l;
        g.wt   = 0.05f * YMAX + 0.5f * l;
        g.wb   = 0.95f * YMAX - 0.5f * l;
        g.rr   = 1.0f - ((tick_diff[t] <= MTFD) ? 1.0f : 0.0f);  // rerand
        g.sln  = slider_len[t];
        g.scos = scos_in[t];
        g.ssin = ssin_in[t];
        g.isl  = is_slider[t];
        gp[t] = g;
    }
    if (t == 0) { s_px0 = start_pos[0]; s_py0 = start_pos[1]; }
    __syncthreads();

    // ---- Compute: per-row scan, results into staged smem ----
    if (active) {
        const float* __restrict__ v = reinterpret_cast<const float*>(rv);
        float2* __restrict__ so = reinterpret_cast<float2*>(s_out + t * PAD_OUT);

        float px = s_px0, py = s_py0;
        const float invX = 1.0f / XMAX;
        const float invY = 1.0f / YMAX;

#pragma unroll
        for (int k = 0; k < NGS; k++) {
            const GroupP g = gp[k];
            const float rr = g.rr;
            const float nr = 1.0f - rr;

            const float vk  = v[k];         // var[:, k]
            const float vh  = v[10 + k];    // var[:, 10+k]
            const float vk2 = v[20 + k];    // var[:, 20+k]
            const float vh2 = v[30 + k];    // var[:, 30+k]

            const float inv1 = rsqrtf(vk * vk + vk2 * vk2);
            const float ck = vk  * inv1;
            const float sk = vk2 * inv1;
            const float inv2 = rsqrtf(vh * vh + vh2 * vh2);
            const float a = vh  * inv2;     // ckh
            const float b = vh2 * inv2;     // skh

            const float rerand_x = 256.0f + 256.0f * vk;
            const float rerand_y = 192.0f + 192.0f * vk2;

            const float dx = g.l * ck;
            const float dy = g.l * sk;

            const float wv_l  = (px < g.wl) ? 1.0f : 0.0f;
            const float wv_r  = (px > g.wr) ? 1.0f : 0.0f;
            const float wv_xm = ((px > g.wl) && (px < g.wr)) ? 1.0f : 0.0f;
            const float wv_t  = (py < g.wt) ? 1.0f : 0.0f;
            const float wv_b  = (py > g.wb) ? 1.0f : 0.0f;
            const float wv_ym = ((py > g.wt) && (py < g.wb)) ? 1.0f : 0.0f;

            const float adx = fabsf(dx);
            const float ady = fabsf(dy);
            const float x_delta = adx * wv_l - adx * wv_r + dx * wv_xm;
            const float y_delta = ady * wv_t - ady * wv_b + dy * wv_ym;

            const float x = rr * rerand_x + nr * (px + x_delta);
            const float y = rr * rerand_y + nr * (py + y_delta);

            float o0 = x * invX;
            float o1 = y * invY;
            float o2, o3, o4, o5;
            if (g.isl) {
                o2 = a * g.scos - b * g.ssin;
                o3 = a * g.ssin + b * g.scos;
                o4 = (x + a * g.sln) * invX;
                o5 = (y + b * g.sln) * invY;
            } else {
                o2 = rr * a + nr * ck;
                o3 = rr * b + nr * sk;
                o4 = o0;
                o5 = o1;
            }

            so[k * 3 + 0] = make_float2(o0, o1);
            so[k * 3 + 1] = make_float2(o2, o3);
            so[k * 3 + 2] = make_float2(o4, o5);

            // NFSE == False => carry is always (_x, _y)
            px = x;
            py = y;
        }
    }
    __syncthreads();

    // ---- Coalesced flush: 256x30 float2 tile, incremental (r,c) indexing ----
    {
        const size_t f2base = (size_t)blockIdx.x * (ROWS_PER_BLK * 30);  // float2 units
        const size_t f2limit = (size_t)B * 30;
        float2* __restrict__ og = reinterpret_cast<float2*>(out);

        int r = t / 30;          // local row
        int c = t % 30;          // float2 column
#pragma unroll
        for (int it = 0; it < 30; it++) {
            size_t gidx = f2base + (size_t)(it * ROWS_PER_BLK + t);
            if (gidx < f2limit) {
                float2 val = *reinterpret_cast<const float2*>(s_out + r * PAD_OUT + c * 2);
                og[gidx] = val;
            }
            // advance by 256 over a width-30 row space: 256 = 8*30 + 16
            r += 8;
            c += 16;
            if (c >= 30) { c -= 30; r += 1; }
        }
    }
}

extern "C" void kernel_launch(void* const* d_in, const int* in_sizes, int n_in,
                              void* d_out, int out_size)
{
    const float* var        = (const float*)d_in[0];
    const float* slider_len = (const float*)d_in[1];
    const float* scos       = (const float*)d_in[2];
    const float* ssin       = (const float*)d_in[3];
    const float* note_dist  = (const float*)d_in[4];
    const float* tick_diff  = (const float*)d_in[5];
    const float* start_pos  = (const float*)d_in[6];
    const int*   is_slider  = (const int*)d_in[7];
    float* out = (float*)d_out;

    int B = in_sizes[0] / (4 * NGS);

    static bool attr_set = false;
    if (!attr_set) {
        cudaFuncSetAttribute(mapping_kernel,
                             cudaFuncAttributeMaxDynamicSharedMemorySize,
                             SMEM_TOTAL_BYTES);
        attr_set = true;
    }

    int threads = ROWS_PER_BLK;
    int blocks = (B + threads - 1) / threads;
    mapping_kernel<<<blocks, threads, SMEM_TOTAL_BYTES>>>(
        var, slider_len, scos, ssin, note_dist,
        tick_diff, start_pos, is_slider, out, B);
}

// round 12
// speedup vs baseline: 2.8401x; 1.0285x over previous
#include <cuda_runtime.h>
#include <cstddef>

#define NGS 10
#define XMAX 512.0f
#define YMAX 384.0f
#define MTFD 1.0f

#define ROWS_PER_BLK 256
#define PAD_IN  44   // 40+4: 176B rows (16B-aligned), 12t%32 distinct/phase -> conflict-free LDS.128
#define PAD_OUT 62   // 60+2: 8B-aligned float2 rows, 2-way max on STS.64, conflict-free flush
#define SMEM_IN_FLOATS  (ROWS_PER_BLK * PAD_IN)    // 11264 floats = 45056 B
#define SMEM_OUT_FLOATS (ROWS_PER_BLK * PAD_OUT)   // 15872 floats = 63488 B
// Input and output stages are OVERLAID in the same buffer (separated by syncs).
#define SMEM_TOTAL_BYTES (SMEM_OUT_FLOATS * 4)     // 63488 B -> 3 CTAs/SM

struct __align__(8) GroupP {
    float l, wl, wr, wt, wb, rr, sln, scos, ssin;
    int   isl;
};

__global__ __launch_bounds__(256, 3)
void mapping_kernel(const float* __restrict__ var,        // [B, 40]
                    const float* __restrict__ slider_len, // [10]
                    const float* __restrict__ scos_in,    // [10]
                    const float* __restrict__ ssin_in,    // [10]
                    const float* __restrict__ note_dist,  // [10]
                    const float* __restrict__ tick_diff,  // [10]
                    const float* __restrict__ start_pos,  // [2]
                    const int*   __restrict__ is_slider,  // [10]
                    float* __restrict__ out,              // [B, 10, 6]
                    int B)
{
    extern __shared__ float smem[];   // overlaid: [256][44] input, then [256][62] output
    __shared__ GroupP gp[NGS];
    __shared__ float s_px0, s_py0;

    const int t = threadIdx.x;
    const bool full = ((blockIdx.x + 1) * ROWS_PER_BLK) <= B;

    // ---- Per-group broadcast params ----
    if (t < NGS) {
        float l = 1.0f * note_dist[t];        // LMUL = 1.0
        GroupP g;
        g.l    = l;
        g.wl   = 0.05f * XMAX + 0.5f * l;
        g.wr   = 0.95f * XMAX - 0.5f * l;
        g.wt   = 0.05f * YMAX + 0.5f * l;
        g.wb   = 0.95f * YMAX - 0.5f * l;
        g.rr   = 1.0f - ((tick_diff[t] <= MTFD) ? 1.0f : 0.0f);  // rerand
        g.sln  = slider_len[t];
        g.scos = scos_in[t];
        g.ssin = ssin_in[t];
        g.isl  = is_slider[t];
        gp[t] = g;
    }
    if (t == 0) { s_px0 = start_pos[0]; s_py0 = start_pos[1]; }

    // ---- Stage A: cooperative coalesced load 256x40 -> smem[256][44] ----
    {
        const float4* __restrict__ vin = reinterpret_cast<const float4*>(var);
        const size_t f4base = (size_t)blockIdx.x * (ROWS_PER_BLK * 10);
        int r = t / 10;
        int c = t - r * 10;
        if (full) {
#pragma unroll
            for (int it = 0; it < 10; it++) {
                float4 x = vin[f4base + (size_t)(it * ROWS_PER_BLK + t)];
                float4* p = reinterpret_cast<float4*>(smem + r * PAD_IN + c * 4);
                *p = x;
                r += 25; c += 6;
                if (c >= 10) { c -= 10; r += 1; }
            }
        } else {
            const size_t f4limit = (size_t)B * 10;
#pragma unroll
            for (int it = 0; it < 10; it++) {
                size_t gidx = f4base + (size_t)(it * ROWS_PER_BLK + t);
                if (gidx < f4limit) {
                    float4 x = vin[gidx];
                    float4* p = reinterpret_cast<float4*>(smem + r * PAD_IN + c * 4);
                    *p = x;
                }
                r += 25; c += 6;
                if (c >= 10) { c -= 10; r += 1; }
            }
        }
    }
    __syncthreads();

    // ---- Stage B: copy own row to registers (conflict-free LDS.128) ----
    float4 rv[10];
    {
        const float4* __restrict__ myrow =
            reinterpret_cast<const float4*>(smem + t * PAD_IN);
#pragma unroll
        for (int j = 0; j < 10; j++) rv[j] = myrow[j];
    }
    __syncthreads();   // all reads done before output overwrites the buffer

    // ---- Stage C: per-row scan, results into staged smem [256][62] ----
    const bool active = full || (blockIdx.x * ROWS_PER_BLK + t < B);
    if (active) {
        const float* __restrict__ v = reinterpret_cast<const float*>(rv);
        float2* __restrict__ so = reinterpret_cast<float2*>(smem + t * PAD_OUT);

        float px = s_px0, py = s_py0;
        const float invX = 1.0f / XMAX;
        const float invY = 1.0f / YMAX;

#pragma unroll
        for (int k = 0; k < NGS; k++) {
            const GroupP g = gp[k];
            const float rr = g.rr;
            const float nr = 1.0f - rr;

            const float vk  = v[k];         // var[:, k]
            const float vh  = v[10 + k];    // var[:, 10+k]
            const float vk2 = v[20 + k];    // var[:, 20+k]
            const float vh2 = v[30 + k];    // var[:, 30+k]

            const float inv1 = rsqrtf(vk * vk + vk2 * vk2);
            const float ck = vk  * inv1;
            const float sk = vk2 * inv1;
            const float inv2 = rsqrtf(vh * vh + vh2 * vh2);
            const float a = vh  * inv2;     // ckh
            const float b = vh2 * inv2;     // skh

            const float rerand_x = 256.0f + 256.0f * vk;
            const float rerand_y = 192.0f + 192.0f * vk2;

            const float dx = g.l * ck;
            const float dy = g.l * sk;

            const float wv_l  = (px < g.wl) ? 1.0f : 0.0f;
            const float wv_r  = (px > g.wr) ? 1.0f : 0.0f;
            const float wv_xm = ((px > g.wl) && (px < g.wr)) ? 1.0f : 0.0f;
            const float wv_t  = (py < g.wt) ? 1.0f : 0.0f;
            const float wv_b  = (py > g.wb) ? 1.0f : 0.0f;
            const float wv_ym = ((py > g.wt) && (py < g.wb)) ? 1.0f : 0.0f;

            const float adx = fabsf(dx);
            const float ady = fabsf(dy);
            const float x_delta = adx * wv_l - adx * wv_r + dx * wv_xm;
            const float y_delta = ady * wv_t - ady * wv_b + dy * wv_ym;

            const float x = rr * rerand_x + nr * (px + x_delta);
            const float y = rr * rerand_y + nr * (py + y_delta);

            float o0 = x * invX;
            float o1 = y * invY;
            float o2, o3, o4, o5;
            if (g.isl) {
                o2 = a * g.scos - b * g.ssin;
                o3 = a * g.ssin + b * g.scos;
                o4 = (x + a * g.sln) * invX;
                o5 = (y + b * g.sln) * invY;
            } else {
                o2 = rr * a + nr * ck;
                o3 = rr * b + nr * sk;
                o4 = o0;
                o5 = o1;
            }

            so[k * 3 + 0] = make_float2(o0, o1);
            so[k * 3 + 1] = make_float2(o2, o3);
            so[k * 3 + 2] = make_float2(o4, o5);

            // NFSE == False => carry is always (_x, _y)
            px = x;
            py = y;
        }
    }
    __syncthreads();

    // ---- Stage D: coalesced flush of the 256x30 float2 tile ----
    {
        const size_t f2base = (size_t)blockIdx.x * (ROWS_PER_BLK * 30);
        float2* __restrict__ og = reinterpret_cast<float2*>(out);

        int r = t / 30;
        int c = t - r * 30;
        if (full) {
#pragma unroll
            for (int it = 0; it < 30; it++) {
                float2 val = *reinterpret_cast<const float2*>(smem + r * PAD_OUT + c * 2);
                og[f2base + (size_t)(it * ROWS_PER_BLK + t)] = val;
                r += 8; c += 16;
                if (c >= 30) { c -= 30; r += 1; }
            }
        } else {
            const size_t f2limit = (size_t)B * 30;
#pragma unroll
            for (int it = 0; it < 30; it++) {
                size_t gidx = f2base + (size_t)(it * ROWS_PER_BLK + t);
                if (gidx < f2limit) {
                    float2 val = *reinterpret_cast<const float2*>(smem + r * PAD_OUT + c * 2);
                    og[gidx] = val;
                }
                r += 8; c += 16;
                if (c >= 30) { c -= 30; r += 1; }
            }
        }
    }
}

extern "C" void kernel_launch(void* const* d_in, const int* in_sizes, int n_in,
                              void* d_out, int out_size)
{
    const float* var        = (const float*)d_in[0];
    const float* slider_len = (const float*)d_in[1];
    const float* scos       = (const float*)d_in[2];
    const float* ssin       = (const float*)d_in[3];
    const float* note_dist  = (const float*)d_in[4];
    const float* tick_diff  = (const float*)d_in[5];
    const float* start_pos  = (const float*)d_in[6];
    const int*   is_slider  = (const int*)d_in[7];
    float* out = (float*)d_out;

    int B = in_sizes[0] / (4 * NGS);

    static bool attr_set = false;
    if (!attr_set) {
        cudaFuncSetAttribute(mapping_kernel,
                             cudaFuncAttributeMaxDynamicSharedMemorySize,
                             SMEM_TOTAL_BYTES);
        attr_set = true;
    }

    int threads = ROWS_PER_BLK;
    int blocks = (B + threads - 1) / threads;
    mapping_kernel<<<blocks, threads, SMEM_TOTAL_BYTES>>>(
        var, slider_len, scos, ssin, note_dist,
        tick_diff, start_pos, is_slider, out, B);
}

// round 14
// speedup vs baseline: 3.2546x; 1.1459x over previous
#include <cuda_runtime.h>
#include <cstdint>
#include <cstddef>

#define NGS 10
#define XMAX 512.0f
#define YMAX 384.0f
#define MTFD 1.0f

#define ROWS_PER_BLK 256
#define IN_FLOATS_PER_ROW  40
#define OUT_FLOATS_PER_ROW 60
#define IN_TILE_BYTES  (ROWS_PER_BLK * IN_FLOATS_PER_ROW * 4)    // 40960
#define OUT_TILE_BYTES (ROWS_PER_BLK * OUT_FLOATS_PER_ROW * 4)   // 61440
// in/out overlaid in one buffer (input dead after register copy)
#define SMEM_TOTAL_BYTES OUT_TILE_BYTES                          // 61440 -> 3 CTAs/SM

struct __align__(8) GroupP {
    float l, wl, wr, wt, wb, rr, sln, scos, ssin;
    int   isl;
};

__device__ __forceinline__ uint32_t smem_u32(const void* p) {
    uint32_t a;
    asm("{ .reg .u64 t; cvta.to.shared.u64 t, %1; cvt.u32.u64 %0, t; }"
        : "=r"(a) : "l"(p));
    return a;
}

__global__ __launch_bounds__(256, 3)
void mapping_kernel(const float* __restrict__ var,        // [B, 40]
                    const float* __restrict__ slider_len, // [10]
                    const float* __restrict__ scos_in,    // [10]
                    const float* __restrict__ ssin_in,    // [10]
                    const float* __restrict__ note_dist,  // [10]
                    const float* __restrict__ tick_diff,  // [10]
                    const float* __restrict__ start_pos,  // [2]
                    const int*   __restrict__ is_slider,  // [10]
                    float* __restrict__ out,              // [B, 10, 6]
                    int B)
{
    extern __shared__ float smem[];   // overlaid: [256][40] in, then [256][60] out
    __shared__ GroupP gp[NGS];
    __shared__ float s_px0, s_py0;
    __shared__ alignas(8) unsigned long long mbar;

    const int t = threadIdx.x;
    const bool full = ((blockIdx.x + 1) * ROWS_PER_BLK) <= B;
    const uint32_t s_base = smem_u32(smem);
    const uint32_t s_mbar = smem_u32(&mbar);

    // ---- Per-group broadcast params ----
    if (t < NGS) {
        float l = 1.0f * note_dist[t];        // LMUL = 1.0
        GroupP g;
        g.l    = l;
        g.wl   = 0.05f * XMAX + 0.5f * l;
        g.wr   = 0.95f * XMAX - 0.5f * l;
        g.wt   = 0.05f * YMAX + 0.5f * l;
        g.wb   = 0.95f * YMAX - 0.5f * l;
        g.rr   = 1.0f - ((tick_diff[t] <= MTFD) ? 1.0f : 0.0f);  // rerand
        g.sln  = slider_len[t];
        g.scos = scos_in[t];
        g.ssin = ssin_in[t];
        g.isl  = is_slider[t];
        gp[t] = g;
    }
    if (t == 0) {
        s_px0 = start_pos[0]; s_py0 = start_pos[1];
        asm volatile("mbarrier.init.shared.b64 [%0], 1;" :: "r"(s_mbar) : "memory");
    }
    __syncthreads();   // mbar + gp visible

    float4 rv[10];

    if (full) {
        // ---- Stage A: single TMA bulk load of the 40KB input tile ----
        if (t == 0) {
            asm volatile("mbarrier.arrive.expect_tx.shared.b64 _, [%0], %1;"
                         :: "r"(s_mbar), "r"((uint32_t)IN_TILE_BYTES) : "memory");
            const float* gsrc = var + (size_t)blockIdx.x * (ROWS_PER_BLK * IN_FLOATS_PER_ROW);
            asm volatile(
                "cp.async.bulk.shared::cta.global.mbarrier::complete_tx::bytes [%0], [%1], %2, [%3];"
                :: "r"(s_base), "l"(gsrc), "r"((uint32_t)IN_TILE_BYTES), "r"(s_mbar)
                : "memory");
        }
        // wait (parity 0)
        {
            uint32_t done;
            asm volatile(
                "{\n\t.reg .pred p;\n\t"
                "mbarrier.try_wait.parity.shared.b64 p, [%1], 0;\n\t"
                "selp.b32 %0, 1, 0, p;\n\t}"
                : "=r"(done) : "r"(s_mbar) : "memory");
            while (!done) {
                asm volatile(
                    "{\n\t.reg .pred p;\n\t"
                    "mbarrier.try_wait.parity.shared.b64 p, [%1], 0;\n\t"
                    "selp.b32 %0, 1, 0, p;\n\t}"
                    : "=r"(done) : "r"(s_mbar) : "memory");
            }
        }
        // ---- Stage B: own row -> registers (10 x LDS.128, 2-way conflicts) ----
        const float4* __restrict__ myrow =
            reinterpret_cast<const float4*>(smem + t * IN_FLOATS_PER_ROW);
#pragma unroll
        for (int j = 0; j < 10; j++) rv[j] = myrow[j];
        __syncthreads();   // all rows consumed before output overwrites buffer
    } else {
        // tail-block fallback (never taken for B % 256 == 0): direct row load
        const int row = blockIdx.x * ROWS_PER_BLK + t;
        if (row < B) {
            const float4* __restrict__ vin =
                reinterpret_cast<const float4*>(var) + (size_t)row * 10;
#pragma unroll
            for (int j = 0; j < 10; j++) rv[j] = vin[j];
        }
        __syncthreads();
    }

    // ---- Stage C: scan; stage full 60-float rows (3x STS.128 per 2 k-steps) ----
    const bool active = full || (blockIdx.x * ROWS_PER_BLK + t < B);
    if (active) {
        const float* __restrict__ v = reinterpret_cast<const float*>(rv);
        float4* __restrict__ so4 = reinterpret_cast<float4*>(smem + t * OUT_FLOATS_PER_ROW);

        float px = s_px0, py = s_py0;
        const float invX = 1.0f / XMAX;
        const float invY = 1.0f / YMAX;
        float obuf[12];

#pragma unroll
        for (int k = 0; k < NGS; k++) {
            const GroupP g = gp[k];
            const float rr = g.rr;
            const float nr = 1.0f - rr;

            const float vk  = v[k];         // var[:, k]
            const float vh  = v[10 + k];    // var[:, 10+k]
            const float vk2 = v[20 + k];    // var[:, 20+k]
            const float vh2 = v[30 + k];    // var[:, 30+k]

            const float inv1 = rsqrtf(vk * vk + vk2 * vk2);
            const float ck = vk  * inv1;
            const float sk = vk2 * inv1;
            const float inv2 = rsqrtf(vh * vh + vh2 * vh2);
            const float a = vh  * inv2;     // ckh
            const float b = vh2 * inv2;     // skh

            const float rerand_x = 256.0f + 256.0f * vk;
            const float rerand_y = 192.0f + 192.0f * vk2;

            const float dx = g.l * ck;
            const float dy = g.l * sk;

            const float wv_l  = (px < g.wl) ? 1.0f : 0.0f;
            const float wv_r  = (px > g.wr) ? 1.0f : 0.0f;
            const float wv_xm = ((px > g.wl) && (px < g.wr)) ? 1.0f : 0.0f;
            const float wv_t  = (py < g.wt) ? 1.0f : 0.0f;
            const float wv_b  = (py > g.wb) ? 1.0f : 0.0f;
            const float wv_ym = ((py > g.wt) && (py < g.wb)) ? 1.0f : 0.0f;

            const float adx = fabsf(dx);
            const float ady = fabsf(dy);
            const float x_delta = adx * wv_l - adx * wv_r + dx * wv_xm;
            const float y_delta = ady * wv_t - ady * wv_b + dy * wv_ym;

            const float x = rr * rerand_x + nr * (px + x_delta);
            const float y = rr * rerand_y + nr * (py + y_delta);

            float o0 = x * invX;
            float o1 = y * invY;
            float o2, o3, o4, o5;
            if (g.isl) {
                o2 = a * g.scos - b * g.ssin;
                o3 = a * g.ssin + b * g.scos;
                o4 = (x + a * g.sln) * invX;
                o5 = (y + b * g.sln) * invY;
            } else {
                o2 = rr * a + nr * ck;
                o3 = rr * b + nr * sk;
                o4 = o0;
                o5 = o1;
            }

            const int half = (k & 1) * 6;
            obuf[half + 0] = o0; obuf[half + 1] = o1; obuf[half + 2] = o2;
            obuf[half + 3] = o3; obuf[half + 4] = o4; obuf[half + 5] = o5;
            if (k & 1) {
                const int base = (k >> 1) * 3;     // 3 float4 per 2 groups
                so4[base + 0] = make_float4(obuf[0], obuf[1], obuf[2],  obuf[3]);
                so4[base + 1] = make_float4(obuf[4], obuf[5], obuf[6],  obuf[7]);
                so4[base + 2] = make_float4(obuf[8], obuf[9], obuf[10], obuf[11]);
            }

            // NFSE == False => carry is always (_x, _y)
            px = x;
            py = y;
        }
    }

    // order generic smem writes before async-proxy TMA read
    asm volatile("fence.proxy.async.shared::cta;" ::: "memory");
    __syncthreads();

    if (full) {
        // ---- Stage D: single TMA bulk store of the 60KB output tile ----
        if (t == 0) {
            float* gdst = out + (size_t)blockIdx.x * (ROWS_PER_BLK * OUT_FLOATS_PER_ROW);
            asm volatile(
                "cp.async.bulk.global.shared::cta.bulk_group [%0], [%1], %2;"
                :: "l"(gdst), "r"(s_base), "r"((uint32_t)OUT_TILE_BYTES)
                : "memory");
            asm volatile("cp.async.bulk.commit_group;" ::: "memory");
            asm volatile("cp.async.bulk.wait_group 0;" ::: "memory");
        }
    } else {
        // fallback flush: guarded coalesced float2 stores
        const size_t f2base = (size_t)blockIdx.x * (ROWS_PER_BLK * 30);
        const size_t f2limit = (size_t)B * 30;
        float2* __restrict__ og = reinterpret_cast<float2*>(out);
        int r = t / 30;
        int c = t - r * 30;
#pragma unroll
        for (int it = 0; it < 30; it++) {
            size_t gidx = f2base + (size_t)(it * ROWS_PER_BLK + t);
            if (gidx < f2limit) {
                float2 val = *reinterpret_cast<const float2*>(
                    smem + r * OUT_FLOATS_PER_ROW + c * 2);
                og[gidx] = val;
            }
            r += 8; c += 16;
            if (c >= 30) { c -= 30; r += 1; }
        }
    }
}

extern "C" void kernel_launch(void* const* d_in, const int* in_sizes, int n_in,
                              void* d_out, int out_size)
{
    const float* var        = (const float*)d_in[0];
    const float* slider_len = (const float*)d_in[1];
    const float* scos       = (const float*)d_in[2];
    const float* ssin       = (const float*)d_in[3];
    const float* note_dist  = (const float*)d_in[4];
    const float* tick_diff  = (const float*)d_in[5];
    const float* start_pos  = (const float*)d_in[6];
    const int*   is_slider  = (const int*)d_in[7];
    float* out = (float*)d_out;

    int B = in_sizes[0] / (4 * NGS);

    static bool attr_set = false;
    if (!attr_set) {
        cudaFuncSetAttribute(mapping_kernel,
                             cudaFuncAttributeMaxDynamicSharedMemorySize,
                             SMEM_TOTAL_BYTES);
        attr_set = true;
    }

    int threads = ROWS_PER_BLK;
    int blocks = (B + threads - 1) / threads;
    mapping_kernel<<<blocks, threads, SMEM_TOTAL_BYTES>>>(
        var, slider_len, scos, ssin, note_dist,
        tick_diff, start_pos, is_slider, out, B);
}

// round 17
// speedup vs baseline: 3.3439x; 1.0274x over previous
#include <cuda_runtime.h>
#include <cstdint>
#include <cstddef>

#define NGS 10
#define XMAX 512.0f
#define YMAX 384.0f
#define MTFD 1.0f

#define ROWS_PER_BLK 128
#define IN_FLOATS_PER_ROW  40
#define OUT_FLOATS_PER_ROW 60
#define IN_TILE_BYTES  (ROWS_PER_BLK * IN_FLOATS_PER_ROW * 4)    // 20480
#define OUT_TILE_BYTES (ROWS_PER_BLK * OUT_FLOATS_PER_ROW * 4)   // 30720
// in/out overlaid in one buffer (input dead after register copy)
#define SMEM_TOTAL_BYTES OUT_TILE_BYTES                          // 30720 -> 7 CTAs/SM

struct __align__(8) GroupP {
    float l, wl, wr, wt, wb, rr, sln, scos, ssin;
    int   isl;
};

__device__ __forceinline__ uint32_t smem_u32(const void* p) {
    uint32_t a;
    asm("{ .reg .u64 t; cvta.to.shared.u64 t, %1; cvt.u32.u64 %0, t; }"
        : "=r"(a) : "l"(p));
    return a;
}

__global__ __launch_bounds__(ROWS_PER_BLK, 7)
void mapping_kernel(const float* __restrict__ var,        // [B, 40]
                    const float* __restrict__ slider_len, // [10]
                    const float* __restrict__ scos_in,    // [10]
                    const float* __restrict__ ssin_in,    // [10]
                    const float* __restrict__ note_dist,  // [10]
                    const float* __restrict__ tick_diff,  // [10]
                    const float* __restrict__ start_pos,  // [2]
                    const int*   __restrict__ is_slider,  // [10]
                    float* __restrict__ out,              // [B, 10, 6]
                    int B)
{
    extern __shared__ float smem[];   // overlaid: [128][40] in, then [128][60] out
    __shared__ GroupP gp[NGS];
    __shared__ float s_px0, s_py0;
    __shared__ alignas(8) unsigned long long mbar;

    const int t = threadIdx.x;
    const bool full = ((blockIdx.x + 1) * ROWS_PER_BLK) <= B;
    const uint32_t s_base = smem_u32(smem);
    const uint32_t s_mbar = smem_u32(&mbar);

    // ---- Per-group broadcast params ----
    if (t < NGS) {
        float l = 1.0f * note_dist[t];        // LMUL = 1.0
        GroupP g;
        g.l    = l;
        g.wl   = 0.05f * XMAX + 0.5f * l;
        g.wr   = 0.95f * XMAX - 0.5f * l;
        g.wt   = 0.05f * YMAX + 0.5f * l;
        g.wb   = 0.95f * YMAX - 0.5f * l;
        g.rr   = 1.0f - ((tick_diff[t] <= MTFD) ? 1.0f : 0.0f);  // rerand
        g.sln  = slider_len[t];
        g.scos = scos_in[t];
        g.ssin = ssin_in[t];
        g.isl  = is_slider[t];
        gp[t] = g;
    }
    if (t == 0) {
        s_px0 = start_pos[0]; s_py0 = start_pos[1];
        asm volatile("mbarrier.init.shared.b64 [%0], 1;" :: "r"(s_mbar) : "memory");
    }
    __syncthreads();   // mbar + gp visible

    float4 rv[10];

    if (full) {
        // ---- Stage A: single TMA bulk load of the 20KB input tile ----
        if (t == 0) {
            asm volatile("mbarrier.arrive.expect_tx.shared.b64 _, [%0], %1;"
                         :: "r"(s_mbar), "r"((uint32_t)IN_TILE_BYTES) : "memory");
            const float* gsrc = var + (size_t)blockIdx.x * (ROWS_PER_BLK * IN_FLOATS_PER_ROW);
            asm volatile(
                "cp.async.bulk.shared::cta.global.mbarrier::complete_tx::bytes [%0], [%1], %2, [%3];"
                :: "r"(s_base), "l"(gsrc), "r"((uint32_t)IN_TILE_BYTES), "r"(s_mbar)
                : "memory");
        }
        // wait (parity 0)
        {
            uint32_t done;
            asm volatile(
                "{\n\t.reg .pred p;\n\t"
                "mbarrier.try_wait.parity.shared.b64 p, [%1], 0;\n\t"
                "selp.b32 %0, 1, 0, p;\n\t}"
                : "=r"(done) : "r"(s_mbar) : "memory");
            while (!done) {
                asm volatile(
                    "{\n\t.reg .pred p;\n\t"
                    "mbarrier.try_wait.parity.shared.b64 p, [%1], 0;\n\t"
                    "selp.b32 %0, 1, 0, p;\n\t}"
                    : "=r"(done) : "r"(s_mbar) : "memory");
            }
        }
        // ---- Stage B: own row -> registers (10 x LDS.128, 2-way conflicts) ----
        const float4* __restrict__ myrow =
            reinterpret_cast<const float4*>(smem + t * IN_FLOATS_PER_ROW);
#pragma unroll
        for (int j = 0; j < 10; j++) rv[j] = myrow[j];
        __syncthreads();   // all rows consumed before output overwrites buffer
    } else {
        // tail-block fallback (never taken for B % 128 == 0): direct row load
        const int row = blockIdx.x * ROWS_PER_BLK + t;
        if (row < B) {
            const float4* __restrict__ vin =
                reinterpret_cast<const float4*>(var) + (size_t)row * 10;
#pragma unroll
            for (int j = 0; j < 10; j++) rv[j] = vin[j];
        }
        __syncthreads();
    }

    // ---- Stage C: scan; stage full 60-float rows (3x STS.128 per 2 k-steps) ----
    const bool active = full || (blockIdx.x * ROWS_PER_BLK + t < B);
    if (active) {
        const float* __restrict__ v = reinterpret_cast<const float*>(rv);
        float4* __restrict__ so4 = reinterpret_cast<float4*>(smem + t * OUT_FLOATS_PER_ROW);

        float px = s_px0, py = s_py0;
        const float invX = 1.0f / XMAX;
        const float invY = 1.0f / YMAX;
        float obuf[12];

#pragma unroll
        for (int k = 0; k < NGS; k++) {
            const GroupP g = gp[k];
            const float rr = g.rr;
            const float nr = 1.0f - rr;

            const float vk  = v[k];         // var[:, k]
            const float vh  = v[10 + k];    // var[:, 10+k]
            const float vk2 = v[20 + k];    // var[:, 20+k]
            const float vh2 = v[30 + k];    // var[:, 30+k]

            const float inv1 = rsqrtf(vk * vk + vk2 * vk2);
            const float ck = vk  * inv1;
            const float sk = vk2 * inv1;
            const float inv2 = rsqrtf(vh * vh + vh2 * vh2);
            const float a = vh  * inv2;     // ckh
            const float b = vh2 * inv2;     // skh

            const float rerand_x = 256.0f + 256.0f * vk;
            const float rerand_y = 192.0f + 192.0f * vk2;

            const float dx = g.l * ck;
            const float dy = g.l * sk;

            const float wv_l  = (px < g.wl) ? 1.0f : 0.0f;
            const float wv_r  = (px > g.wr) ? 1.0f : 0.0f;
            const float wv_xm = ((px > g.wl) && (px < g.wr)) ? 1.0f : 0.0f;
            const float wv_t  = (py < g.wt) ? 1.0f : 0.0f;
            const float wv_b  = (py > g.wb) ? 1.0f : 0.0f;
            const float wv_ym = ((py > g.wt) && (py < g.wb)) ? 1.0f : 0.0f;

            const float adx = fabsf(dx);
            const float ady = fabsf(dy);
            const float x_delta = adx * wv_l - adx * wv_r + dx * wv_xm;
            const float y_delta = ady * wv_t - ady * wv_b + dy * wv_ym;

            const float x = rr * rerand_x + nr * (px + x_delta);
            const float y = rr * rerand_y + nr * (py + y_delta);

            float o0 = x * invX;
            float o1 = y * invY;
            float o2, o3, o4, o5;
            if (g.isl) {
                o2 = a * g.scos - b * g.ssin;
                o3 = a * g.ssin + b * g.scos;
                o4 = (x + a * g.sln) * invX;
                o5 = (y + b * g.sln) * invY;
            } else {
                o2 = rr * a + nr * ck;
                o3 = rr * b + nr * sk;
                o4 = o0;
                o5 = o1;
            }

            const int half = (k & 1) * 6;
            obuf[half + 0] = o0; obuf[half + 1] = o1; obuf[half + 2] = o2;
            obuf[half + 3] = o3; obuf[half + 4] = o4; obuf[half + 5] = o5;
            if (k & 1) {
                const int base = (k >> 1) * 3;     // 3 float4 per 2 groups
                so4[base + 0] = make_float4(obuf[0], obuf[1], obuf[2],  obuf[3]);
                so4[base + 1] = make_float4(obuf[4], obuf[5], obuf[6],  obuf[7]);
                so4[base + 2] = make_float4(obuf[8], obuf[9], obuf[10], obuf[11]);
            }

            // NFSE == False => carry is always (_x, _y)
            px = x;
            py = y;
        }
    }

    // order generic smem writes before async-proxy TMA read
    asm volatile("fence.proxy.async.shared::cta;" ::: "memory");
    __syncthreads();

    if (full) {
        // ---- Stage D: single TMA bulk store of the 30KB output tile ----
        if (t == 0) {
            float* gdst = out + (size_t)blockIdx.x * (ROWS_PER_BLK * OUT_FLOATS_PER_ROW);
            asm volatile(
                "cp.async.bulk.global.shared::cta.bulk_group [%0], [%1], %2;"
                :: "l"(gdst), "r"(s_base), "r"((uint32_t)OUT_TILE_BYTES)
                : "memory");
            asm volatile("cp.async.bulk.commit_group;" ::: "memory");
            asm volatile("cp.async.bulk.wait_group 0;" ::: "memory");
        }
    } else {
        // fallback flush: guarded coalesced float2 stores
        const size_t f2base = (size_t)blockIdx.x * (ROWS_PER_BLK * 30);
        const size_t f2limit = (size_t)B * 30;
        float2* __restrict__ og = reinterpret_cast<float2*>(out);
        int r = t / 30;
        int c = t - r * 30;
#pragma unroll
        for (int it = 0; it < 60; it++) {
            size_t gidx = f2base + (size_t)(it * ROWS_PER_BLK + t);
            if (gidx < f2limit) {
                float2 val = *reinterpret_cast<const float2*>(
                    smem + r * OUT_FLOATS_PER_ROW + c * 2);
                og[gidx] = val;
            }
            // advance by 128 over a width-30 row space: 128 = 4*30 + 8
            r += 4; c += 8;
            if (c >= 30) { c -= 30; r += 1; }
        }
    }
}

extern "C" void kernel_launch(void* const* d_in, const int* in_sizes, int n_in,
                              void* d_out, int out_size)
{
    const float* var        = (const float*)d_in[0];
    const float* slider_len = (const float*)d_in[1];
    const float* scos       = (const float*)d_in[2];
    const float* ssin       = (const float*)d_in[3];
    const float* note_dist  = (const float*)d_in[4];
    const float* tick_diff  = (const float*)d_in[5];
    const float* start_pos  = (const float*)d_in[6];
    const int*   is_slider  = (const int*)d_in[7];
    float* out = (float*)d_out;

    int B = in_sizes[0] / (4 * NGS);

    static bool attr_set = false;
    if (!attr_set) {
        cudaFuncSetAttribute(mapping_kernel,
                             cudaFuncAttributeMaxDynamicSharedMemorySize,
                             SMEM_TOTAL_BYTES);
        attr_set = true;
    }

    int threads = ROWS_PER_BLK;
    int blocks = (B + threads - 1) / threads;
    mapping_kernel<<<blocks, threads, SMEM_TOTAL_BYTES>>>(
        var, slider_len, scos, ssin, note_dist,
        tick_diff, start_pos, is_slider, out, B);
}